// round 11
// baseline (speedup 1.0000x reference)
#include <cuda_runtime.h>
#include <cuda_fp16.h>
#include <cstdint>

// Problem shape (fixed per metadata):
//   X0 [4,1024,256] f32, t [4,1] f32, Wc_w [128,256] f32, Wc_b [128] f32,
//   w [128] f32, A [64,128,6] f32, Bp [64,128,6] f32  ->  out [4,1024,64] f32
#define B_   4
#define S_   1024
#define ROWS 4096        // B_*S_
#define DIN  256
#define Q_   128
#define KF   6
#define DOUT 64
#define KSL  1536        // GEMM2: 1 fp16 slot per feature

// Scratch (no device allocs allowed)
__device__ float  g_angle[ROWS * Q_];          // 2 MB
__device__ __half g_bh[DOUT * KSL];            // 192 KB  [d][k] fp16 coeffs

// ---------------------------------------------------------------------------
// m16n8k16 fp16 MMA, fp32 accumulate
// ---------------------------------------------------------------------------
__device__ __forceinline__ void mma16816(float* c, const uint32_t* a,
                                         const uint32_t* b) {
    asm volatile(
        "mma.sync.aligned.m16n8k16.row.col.f32.f16.f16.f32 "
        "{%0,%1,%2,%3}, {%4,%5,%6,%7}, {%8,%9}, {%0,%1,%2,%3};"
        : "+f"(c[0]), "+f"(c[1]), "+f"(c[2]), "+f"(c[3])
        : "r"(a[0]), "r"(a[1]), "r"(a[2]), "r"(a[3]), "r"(b[0]), "r"(b[1]));
}

// ---------------------------------------------------------------------------
// Kernel 1: angle GEMM, 16 rows/CTA x 256 CTAs (grid > 148 SMs -> 2 CTAs/SM
// interleave). Inline W split; K=256 f32 in 8 chunks of 32.
// A slots [xh|xl], B slots [wh|wl]; xh*wh + xh*wl + xl*wh (xl*wl <= 2^-22).
// Tail: 192-element slice of the A,Bp fold (g_bh) per CTA.
// ---------------------------------------------------------------------------
#define KP1 72

__global__ __launch_bounds__(128) void angle_kernel(
    const float* __restrict__ X0, const float* __restrict__ W,
    const float* __restrict__ bias, const float* __restrict__ wvec,
    const float* __restrict__ tvec,
    const float* __restrict__ A, const float* __restrict__ Bp)
{
    __shared__ __align__(16) __half Ws1[Q_][KP1];   // 18 KB
    __shared__ __align__(16) __half Ax1[16][KP1];   //  2.3 KB

    int tid  = threadIdx.x;
    int lane = tid & 31;
    int w    = tid >> 5;              // warp 0..3, q range w*32 .. +31
    int r0   = blockIdx.x * 16;
    int ra   = lane >> 2;
    int cc   = 2 * (lane & 3);

    float acc[4][4] = {};             // [ntile][frag], 1 mtile (16 rows)
    int xrow = tid >> 3;              // A staging row 0..15
    int kgrp = (tid & 7) * 4;         // f32 k offset (4 floats/thread)

    // prologue prefetch chunk 0: X rows + raw W row (q = tid, 32 f32)
    float4 nx = *(const float4*)&X0[(r0 + xrow) * DIN + kgrp];
    float4 nwf[8];
    #pragma unroll
    for (int j = 0; j < 8; j++)
        nwf[j] = *(const float4*)&W[tid * DIN + j * 4];

    for (int c = 0; c < 8; c++) {
        // ---- stage A: split 4 f32 -> xh @ col kgrp, xl @ col 32+kgrp ----
        {
            float xf[4] = {nx.x, nx.y, nx.z, nx.w};
            uint32_t ph[2], pl[2];
            #pragma unroll
            for (int j = 0; j < 2; j++) {
                float a0 = xf[2 * j], a1 = xf[2 * j + 1];
                __half h0 = __float2half_rn(a0);
                __half l0 = __float2half_rn(a0 - __half2float(h0));
                __half h1 = __float2half_rn(a1);
                __half l1 = __float2half_rn(a1 - __half2float(h1));
                __half2 hh = __halves2half2(h0, h1);
                __half2 ll = __halves2half2(l0, l1);
                ph[j] = *(uint32_t*)&hh;
                pl[j] = *(uint32_t*)&ll;
            }
            *(uint2*)&Ax1[xrow][kgrp]      = make_uint2(ph[0], ph[1]);
            *(uint2*)&Ax1[xrow][32 + kgrp] = make_uint2(pl[0], pl[1]);
        }
        // ---- stage B: inline split of 32 f32 -> wh cols 0-31, wl 32-63 ----
        {
            const float* wf = (const float*)nwf;
            uint32_t whp[16], wlp[16];
            #pragma unroll
            for (int j = 0; j < 16; j++) {
                float a0 = wf[2 * j], a1 = wf[2 * j + 1];
                __half h0 = __float2half_rn(a0);
                __half l0 = __float2half_rn(a0 - __half2float(h0));
                __half h1 = __float2half_rn(a1);
                __half l1 = __float2half_rn(a1 - __half2float(h1));
                __half2 hh = __halves2half2(h0, h1);
                __half2 ll = __halves2half2(l0, l1);
                whp[j] = *(uint32_t*)&hh;
                wlp[j] = *(uint32_t*)&ll;
            }
            #pragma unroll
            for (int g = 0; g < 4; g++) {
                *(uint4*)&Ws1[tid][g * 8] =
                    make_uint4(whp[4*g], whp[4*g+1], whp[4*g+2], whp[4*g+3]);
                *(uint4*)&Ws1[tid][32 + g * 8] =
                    make_uint4(wlp[4*g], wlp[4*g+1], wlp[4*g+2], wlp[4*g+3]);
            }
        }
        __syncthreads();

        // ---- prefetch next chunk (hidden under MMA) ----
        if (c < 7) {
            nx = *(const float4*)&X0[(r0 + xrow) * DIN + (c + 1) * 32 + kgrp];
            #pragma unroll
            for (int j = 0; j < 8; j++)
                nwf[j] = *(const float4*)&W[tid * DIN + (c + 1) * 32 + j * 4];
        }

        // ---- MMA: 2 ktiles x {xh*wh, xh*wl, xl*wh} x 4n ----
        #pragma unroll
        for (int kt = 0; kt < 2; kt++) {
            int kh = kt * 16 + cc;        // xh / wh cols
            int kl = 32 + kh;             // xl / wl cols
            uint32_t Ah[4], Al[4];
            Ah[0] = *(const uint32_t*)&Ax1[ra][kh];
            Ah[1] = *(const uint32_t*)&Ax1[ra + 8][kh];
            Ah[2] = *(const uint32_t*)&Ax1[ra][kh + 8];
            Ah[3] = *(const uint32_t*)&Ax1[ra + 8][kh + 8];
            Al[0] = *(const uint32_t*)&Ax1[ra][kl];
            Al[1] = *(const uint32_t*)&Ax1[ra + 8][kl];
            Al[2] = *(const uint32_t*)&Ax1[ra][kl + 8];
            Al[3] = *(const uint32_t*)&Ax1[ra + 8][kl + 8];
            #pragma unroll
            for (int n = 0; n < 4; n++) {
                int q0 = w * 32 + n * 8 + ra;
                uint32_t Bh[2], Bl[2];
                Bh[0] = *(const uint32_t*)&Ws1[q0][kh];
                Bh[1] = *(const uint32_t*)&Ws1[q0][kh + 8];
                Bl[0] = *(const uint32_t*)&Ws1[q0][kl];
                Bl[1] = *(const uint32_t*)&Ws1[q0][kl + 8];
                mma16816(acc[n], Ah, Bh);   // xh*wh
                mma16816(acc[n], Ah, Bl);   // xh*wl
                mma16816(acc[n], Al, Bh);   // xl*wh
            }
        }
        __syncthreads();
    }

    // ---- epilogue: + bias + w*t -> g_angle (16 rows) ----
    float tb = tvec[r0 >> 10];
    #pragma unroll
    for (int n = 0; n < 4; n++) {
        int q = w * 32 + n * 8 + cc;
        float b0 = __ldg(&bias[q])     + __ldg(&wvec[q]) * tb;
        float b1 = __ldg(&bias[q + 1]) + __ldg(&wvec[q + 1]) * tb;
        int rr = r0 + ra;
        *(float2*)&g_angle[rr * Q_ + q]       = make_float2(acc[n][0] + b0, acc[n][1] + b1);
        *(float2*)&g_angle[(rr + 8) * Q_ + q] = make_float2(acc[n][2] + b0, acc[n][3] + b1);
    }

    // ---- tail: this CTA's 192-element slice of the A,Bp fold (g_bh) ----
    #pragma unroll
    for (int j = 0; j < 2; j++) {
        int idx = j * 128 + tid;
        if (idx < 192) {
            int i = blockIdx.x * 192 + idx;           // 0 .. 49151
            int d   = i / (Q_ * KF);
            int rem = i - d * (Q_ * KF);              // q*6 + h
            float a = A[i], b = Bp[i];
            float sb, cb;
            __sincosf(b, &sb, &cb);
            __half2 hv = __floats2half2_rn(a * cb, a * sb);
            *(uint32_t*)&g_bh[d * KSL + rem * 2] = *(uint32_t*)&hv;
        }
    }
}

// ---------------------------------------------------------------------------
// Kernel 2: fused feature-gen + HMMA GEMM2, 16 rows/CTA x 256 CTAs.
// 8 chunks of 16 q (192 k-slots). Featgen: 2 (row,q) per thread per chunk.
// Warp w: 16 rows x 16 d (1 mtile x 2 ntiles). smem stride 400B.
// ---------------------------------------------------------------------------
#define KPAD   200
#define CHUNK_K 192
#define NCHUNK  8

__global__ __launch_bounds__(128) void fuse_kernel(float* __restrict__ out)
{
    __shared__ __half As[16][KPAD];   //  6.4 KB
    __shared__ __half Bs[64][KPAD];   // 25.6 KB

    int tid  = threadIdx.x;
    int lane = tid & 31;
    int w    = tid >> 5;
    int r0   = blockIdx.x * 16;
    int row  = tid & 15;              // featgen row
    int qg   = tid >> 4;              // featgen q-pair base (q = qg*2, qg*2+1)
    int ra   = lane >> 2;
    int cc   = 2 * (lane & 3);

    float acc[2][4] = {};             // [ntile][frag]

    // prologue prefetch: chunk 0
    uint4 nB[12];
    #pragma unroll
    for (int r = 0; r < 12; r++) {
        int idx = tid + 128 * r;
        int d   = idx / 24;
        int kc  = idx - d * 24;
        nB[r] = *(const uint4*)&g_bh[d * KSL + kc * 8];
    }
    float2 nAng = *(const float2*)&g_angle[(r0 + row) * Q_ + qg * 2];

    for (int c = 0; c < NCHUNK; c++) {
        // ---- features for 2 q's -> fp16, STS ----
        {
            float af[2] = {nAng.x, nAng.y};
            #pragma unroll
            for (int p = 0; p < 2; p++) {
                float a = af[p];
                // Cody-Waite reduction mod 2*pi (C1=6.28125: 9 mantissa bits)
                float n = rintf(a * 0.15915494309189535f);
                float rr = fmaf(n, -6.28125f, a);
                rr = fmaf(n, -1.9353071795864769e-3f, rr);
                float s1, c1;
                __sincosf(rr, &s1, &c1);
                float f[12];
                f[0] = s1; f[1] = c1;
                float sk = s1, ck = c1;
                #pragma unroll
                for (int h = 1; h < KF; h++) {
                    float sn = fmaf(sk, c1, ck * s1);
                    float cn = fmaf(ck, c1, -sk * s1);
                    f[2 * h] = sn; f[2 * h + 1] = cn;
                    sk = sn; ck = cn;
                }
                uint32_t hv[6];
                #pragma unroll
                for (int g = 0; g < 6; g++) {
                    __half2 h2 = __floats2half2_rn(f[2 * g], f[2 * g + 1]);
                    hv[g] = *(uint32_t*)&h2;
                }
                int kl = (qg * 2 + p) * 12;
                uint64_t* dst = (uint64_t*)&As[row][kl];
                dst[0] = (uint64_t)hv[0] | ((uint64_t)hv[1] << 32);
                dst[1] = (uint64_t)hv[2] | ((uint64_t)hv[3] << 32);
                dst[2] = (uint64_t)hv[4] | ((uint64_t)hv[5] << 32);
            }
        }
        // ---- stage B chunk ----
        #pragma unroll
        for (int r = 0; r < 12; r++) {
            int idx = tid + 128 * r;
            int d   = idx / 24;
            int kc  = idx - d * 24;
            *(uint4*)&Bs[d][kc * 8] = nB[r];
        }
        __syncthreads();

        // ---- prefetch next chunk ----
        if (c < NCHUNK - 1) {
            #pragma unroll
            for (int r = 0; r < 12; r++) {
                int idx = tid + 128 * r;
                int d   = idx / 24;
                int kc  = idx - d * 24;
                nB[r] = *(const uint4*)&g_bh[d * KSL + (c + 1) * CHUNK_K + kc * 8];
            }
            nAng = *(const float2*)&g_angle[(r0 + row) * Q_ + (c + 1) * 16 + qg * 2];
        }

        // ---- MMA: 12 ktiles x 2n ----
        #pragma unroll
        for (int kt = 0; kt < 12; kt++) {
            int k0 = kt * 16 + cc;
            uint32_t A0[4];
            A0[0] = *(const uint32_t*)&As[ra][k0];
            A0[1] = *(const uint32_t*)&As[ra + 8][k0];
            A0[2] = *(const uint32_t*)&As[ra][k0 + 8];
            A0[3] = *(const uint32_t*)&As[ra + 8][k0 + 8];
            int d0 = w * 16 + ra;
            uint32_t Bf0[2], Bf1[2];
            Bf0[0] = *(const uint32_t*)&Bs[d0][k0];
            Bf0[1] = *(const uint32_t*)&Bs[d0][k0 + 8];
            Bf1[0] = *(const uint32_t*)&Bs[d0 + 8][k0];
            Bf1[1] = *(const uint32_t*)&Bs[d0 + 8][k0 + 8];
            mma16816(acc[0], A0, Bf0);
            mma16816(acc[1], A0, Bf1);
        }
        __syncthreads();
    }

    // ---- epilogue ----
    int orow = r0 + ra;
    int ocol = w * 16 + cc;
    #pragma unroll
    for (int nt = 0; nt < 2; nt++) {
        int ccg = ocol + nt * 8;
        *(float2*)&out[orow * DOUT + ccg]       = make_float2(acc[nt][0], acc[nt][1]);
        *(float2*)&out[(orow + 8) * DOUT + ccg] = make_float2(acc[nt][2], acc[nt][3]);
    }
}

// ---------------------------------------------------------------------------
extern "C" void kernel_launch(void* const* d_in, const int* in_sizes, int n_in,
                              void* d_out, int out_size) {
    const float* X0   = (const float*)d_in[0];
    const float* tvec = (const float*)d_in[1];
    const float* Wc_w = (const float*)d_in[2];
    const float* Wc_b = (const float*)d_in[3];
    const float* wvec = (const float*)d_in[4];
    const float* A    = (const float*)d_in[5];
    const float* Bp   = (const float*)d_in[6];
    float* out = (float*)d_out;

    angle_kernel<<<ROWS / 16, 128>>>(X0, Wc_w, Wc_b, wvec, tvec, A, Bp);
    fuse_kernel<<<ROWS / 16, 128>>>(out);
}

// round 12
// speedup vs baseline: 1.3560x; 1.3560x over previous
#include <cuda_runtime.h>
#include <cuda_fp16.h>
#include <cstdint>

// Problem shape (fixed per metadata):
//   X0 [4,1024,256] f32, t [4,1] f32, Wc_w [128,256] f32, Wc_b [128] f32,
//   w [128] f32, A [64,128,6] f32, Bp [64,128,6] f32  ->  out [4,1024,64] f32
#define B_   4
#define S_   1024
#define ROWS 4096        // B_*S_
#define DIN  256
#define Q_   128
#define KF   6
#define DOUT 64
#define KSL  1536        // GEMM2: 1 fp16 slot per feature

// Scratch (no device allocs allowed)
__device__ float  g_angle[ROWS * Q_];          // 2 MB
__device__ __half g_bh[DOUT * KSL];            // 192 KB  [d][k] fp16 coeffs

// ---------------------------------------------------------------------------
// m16n8k16 fp16 MMA + ldmatrix helpers
// ---------------------------------------------------------------------------
__device__ __forceinline__ void mma16816(float* c, const uint32_t* a,
                                         const uint32_t* b) {
    asm volatile(
        "mma.sync.aligned.m16n8k16.row.col.f32.f16.f16.f32 "
        "{%0,%1,%2,%3}, {%4,%5,%6,%7}, {%8,%9}, {%0,%1,%2,%3};"
        : "+f"(c[0]), "+f"(c[1]), "+f"(c[2]), "+f"(c[3])
        : "r"(a[0]), "r"(a[1]), "r"(a[2]), "r"(a[3]), "r"(b[0]), "r"(b[1]));
}
__device__ __forceinline__ void ldsm_x4(uint32_t* r, uint32_t addr) {
    asm volatile("ldmatrix.sync.aligned.m8n8.x4.shared.b16 {%0,%1,%2,%3}, [%4];"
                 : "=r"(r[0]), "=r"(r[1]), "=r"(r[2]), "=r"(r[3]) : "r"(addr));
}
__device__ __forceinline__ uint32_t smem_u32(const void* p) {
    uint32_t a;
    asm("{ .reg .u64 t; cvta.to.shared.u64 t, %1; cvt.u32.u64 %0, t; }"
        : "=r"(a) : "l"(p));
    return a;
}

// ---------------------------------------------------------------------------
// Kernel 1: angle GEMM, 128 CTAs x 128 threads, 32 rows/CTA, K=256 f32 in
// 8 chunks of 32. INLINE W split. Double-buffered A/B smem, ONE barrier per
// chunk: stage(c+1) + LDG(c+2) overlap MMA(c). A frags via ldmatrix.x4.
// Products: xh*wh + xh*wl + xl*wh (xl*wl dropped, <=2^-22 rel).
// Tail: 384-element slice of the A,Bp fold (g_bh) per CTA.
// ---------------------------------------------------------------------------
#define KP1 72

__global__ __launch_bounds__(128) void angle_kernel(
    const float* __restrict__ X0, const float* __restrict__ W,
    const float* __restrict__ bias, const float* __restrict__ wvec,
    const float* __restrict__ tvec,
    const float* __restrict__ A, const float* __restrict__ Bp)
{
    __shared__ __align__(16) __half Ws1[2][Q_][KP1];   // 36 KB
    __shared__ __align__(16) __half Ax1[2][32][KP1];   //  9.2 KB

    int tid  = threadIdx.x;
    int lane = tid & 31;
    int w    = tid >> 5;              // warp 0..3, q range w*32 .. +31
    int r0   = blockIdx.x * 32;
    int ra   = lane >> 2;
    int cc   = 2 * (lane & 3);
    int lrow = (lane & 7) + ((lane >> 3) & 1) * 8;   // ldmatrix row-in-tile
    int lco  = (lane >> 4) * 8;                      // ldmatrix col offset

    float acc[2][4][4] = {};          // [mtile][ntile][frag]
    int xrow = tid >> 2;              // A staging row 0..31
    int kgrp = (tid & 3) * 8;         // f32 k offset (8 floats/thread)

    // split 8 f32 of X -> xh cols kgrp.., xl cols 32+kgrp..
    auto stageA = [&](const float4& x0, const float4& x1, int buf) {
        float xf[8] = {x0.x, x0.y, x0.z, x0.w, x1.x, x1.y, x1.z, x1.w};
        uint32_t ph[4], pl[4];
        #pragma unroll
        for (int j = 0; j < 4; j++) {
            float a0 = xf[2 * j], a1 = xf[2 * j + 1];
            __half h0 = __float2half_rn(a0);
            __half l0 = __float2half_rn(a0 - __half2float(h0));
            __half h1 = __float2half_rn(a1);
            __half l1 = __float2half_rn(a1 - __half2float(h1));
            __half2 hh = __halves2half2(h0, h1);
            __half2 ll = __halves2half2(l0, l1);
            ph[j] = *(uint32_t*)&hh;
            pl[j] = *(uint32_t*)&ll;
        }
        *(uint4*)&Ax1[buf][xrow][kgrp]      = make_uint4(ph[0], ph[1], ph[2], ph[3]);
        *(uint4*)&Ax1[buf][xrow][32 + kgrp] = make_uint4(pl[0], pl[1], pl[2], pl[3]);
    };
    // split 32 f32 of W (q = tid) -> wh cols 0-31, wl cols 32-63
    auto stageW = [&](const float4* nwf, int buf) {
        const float* wf = (const float*)nwf;
        uint32_t whp[16], wlp[16];
        #pragma unroll
        for (int j = 0; j < 16; j++) {
            float a0 = wf[2 * j], a1 = wf[2 * j + 1];
            __half h0 = __float2half_rn(a0);
            __half l0 = __float2half_rn(a0 - __half2float(h0));
            __half h1 = __float2half_rn(a1);
            __half l1 = __float2half_rn(a1 - __half2float(h1));
            __half2 hh = __halves2half2(h0, h1);
            __half2 ll = __halves2half2(l0, l1);
            whp[j] = *(uint32_t*)&hh;
            wlp[j] = *(uint32_t*)&ll;
        }
        #pragma unroll
        for (int g = 0; g < 4; g++) {
            *(uint4*)&Ws1[buf][tid][g * 8] =
                make_uint4(whp[4*g], whp[4*g+1], whp[4*g+2], whp[4*g+3]);
            *(uint4*)&Ws1[buf][tid][32 + g * 8] =
                make_uint4(wlp[4*g], wlp[4*g+1], wlp[4*g+2], wlp[4*g+3]);
        }
    };

    // ---- prologue: stage chunk 0, prefetch chunk 1 ----
    float4 nx0 = *(const float4*)&X0[(r0 + xrow) * DIN + kgrp];
    float4 nx1 = *(const float4*)&X0[(r0 + xrow) * DIN + kgrp + 4];
    float4 nwf[8];
    #pragma unroll
    for (int j = 0; j < 8; j++)
        nwf[j] = *(const float4*)&W[tid * DIN + j * 4];
    stageA(nx0, nx1, 0);
    stageW(nwf, 0);
    nx0 = *(const float4*)&X0[(r0 + xrow) * DIN + 32 + kgrp];
    nx1 = *(const float4*)&X0[(r0 + xrow) * DIN + 32 + kgrp + 4];
    #pragma unroll
    for (int j = 0; j < 8; j++)
        nwf[j] = *(const float4*)&W[tid * DIN + 32 + j * 4];
    __syncthreads();

    for (int c = 0; c < 8; c++) {
        // ---- stage chunk c+1 into alt buffers (overlaps MMA below) ----
        if (c < 7) {
            stageA(nx0, nx1, (c + 1) & 1);
            stageW(nwf, (c + 1) & 1);
            if (c < 6) {
                nx0 = *(const float4*)&X0[(r0 + xrow) * DIN + (c + 2) * 32 + kgrp];
                nx1 = *(const float4*)&X0[(r0 + xrow) * DIN + (c + 2) * 32 + kgrp + 4];
                #pragma unroll
                for (int j = 0; j < 8; j++)
                    nwf[j] = *(const float4*)&W[tid * DIN + (c + 2) * 32 + j * 4];
            }
        }

        // ---- MMA(c): 2 ktiles x {xh*wh, xh*wl, xl*wh} x 2m x 4n ----
        uint32_t axb = smem_u32(&Ax1[c & 1][0][0]);
        const __half (*Ws)[KP1] = Ws1[c & 1];
        #pragma unroll
        for (int kt = 0; kt < 2; kt++) {
            int khb = kt * 16;            // xh col base
            int klb = 32 + kt * 16;       // xl col base
            uint32_t A0h[4], A1h[4], A0l[4], A1l[4];
            ldsm_x4(A0h, axb + (uint32_t)((lrow * KP1 + khb + lco) * 2));
            ldsm_x4(A1h, axb + (uint32_t)(((16 + lrow) * KP1 + khb + lco) * 2));
            ldsm_x4(A0l, axb + (uint32_t)((lrow * KP1 + klb + lco) * 2));
            ldsm_x4(A1l, axb + (uint32_t)(((16 + lrow) * KP1 + klb + lco) * 2));
            int kh = khb + cc, kl = klb + cc;
            #pragma unroll
            for (int n = 0; n < 4; n++) {
                int q0 = w * 32 + n * 8 + ra;
                uint32_t Bh[2], Bl[2];
                Bh[0] = *(const uint32_t*)&Ws[q0][kh];
                Bh[1] = *(const uint32_t*)&Ws[q0][kh + 8];
                Bl[0] = *(const uint32_t*)&Ws[q0][kl];
                Bl[1] = *(const uint32_t*)&Ws[q0][kl + 8];
                mma16816(acc[0][n], A0h, Bh);   // xh*wh
                mma16816(acc[1][n], A1h, Bh);
                mma16816(acc[0][n], A0h, Bl);   // xh*wl
                mma16816(acc[1][n], A1h, Bl);
                mma16816(acc[0][n], A0l, Bh);   // xl*wh
                mma16816(acc[1][n], A1l, Bh);
            }
        }
        __syncthreads();
    }

    // ---- epilogue: + bias + w*t -> g_angle ----
    float tb = tvec[r0 >> 10];
    #pragma unroll
    for (int n = 0; n < 4; n++) {
        int q = w * 32 + n * 8 + cc;
        float b0 = __ldg(&bias[q])     + __ldg(&wvec[q]) * tb;
        float b1 = __ldg(&bias[q + 1]) + __ldg(&wvec[q + 1]) * tb;
        #pragma unroll
        for (int m = 0; m < 2; m++) {
            int rr = r0 + m * 16 + ra;
            float* a4 = acc[m][n];
            *(float2*)&g_angle[rr * Q_ + q]       = make_float2(a4[0] + b0, a4[1] + b1);
            *(float2*)&g_angle[(rr + 8) * Q_ + q] = make_float2(a4[2] + b0, a4[3] + b1);
        }
    }

    // ---- tail: this CTA's 384-element slice of the A,Bp fold (g_bh) ----
    #pragma unroll
    for (int j = 0; j < 3; j++) {
        int i = blockIdx.x * 384 + j * 128 + tid;     // 0 .. 49151
        int d   = i / (Q_ * KF);
        int rem = i - d * (Q_ * KF);                  // q*6 + h
        float a = A[i], b = Bp[i];
        float sb, cb;
        __sincosf(b, &sb, &cb);
        __half2 hv = __floats2half2_rn(a * cb, a * sb);
        *(uint32_t*)&g_bh[d * KSL + rem * 2] = *(uint32_t*)&hv;
    }
}

// ---------------------------------------------------------------------------
// Kernel 2: fused feature-gen + HMMA GEMM2, 128 CTAs x 128 threads,
// 32 rows/CTA. 16 chunks of 8 q (96 k-slots, 6 ktiles). Fully double-
// buffered (As, Bs), ONE barrier per chunk: featgen(c+1) + B-stage(c+1) +
// LDG(c+2) all overlap MMA(c). A frags via ldmatrix.x4.
// ---------------------------------------------------------------------------
#define KPD2   104
#define CHUNK_K 96
#define NCHUNK  16

__global__ __launch_bounds__(128) void fuse_kernel(float* __restrict__ out)
{
    __shared__ __align__(16) __half As[2][32][KPD2];   // 13.3 KB
    __shared__ __align__(16) __half Bs[2][64][KPD2];   // 26.6 KB

    int tid  = threadIdx.x;
    int lane = tid & 31;
    int w    = tid >> 5;
    int r0   = blockIdx.x * 32;
    int row  = tid & 31;              // featgen row
    int qlb  = w * 2;                 // featgen local-q base (2 q per thread)
    int ra   = lane >> 2;
    int cc   = 2 * (lane & 3);
    int lrow = (lane & 7) + ((lane >> 3) & 1) * 8;
    int lco  = (lane >> 4) * 8;

    float acc[2][2][4] = {};

    // featgen for local q pair at chunk c from angle pair -> As[buf]
    auto featgen = [&](float2 ang, int buf) {
        float af[2] = {ang.x, ang.y};
        #pragma unroll
        for (int p = 0; p < 2; p++) {
            float a = af[p];
            // Cody-Waite reduction mod 2*pi (C1=6.28125: 9 mantissa bits)
            float n = rintf(a * 0.15915494309189535f);
            float rr = fmaf(n, -6.28125f, a);
            rr = fmaf(n, -1.9353071795864769e-3f, rr);
            float s1, c1;
            __sincosf(rr, &s1, &c1);
            float f[12];
            f[0] = s1; f[1] = c1;
            float sk = s1, ck = c1;
            #pragma unroll
            for (int h = 1; h < KF; h++) {
                float sn = fmaf(sk, c1, ck * s1);
                float cn = fmaf(ck, c1, -sk * s1);
                f[2 * h] = sn; f[2 * h + 1] = cn;
                sk = sn; ck = cn;
            }
            uint32_t hv[6];
            #pragma unroll
            for (int g = 0; g < 6; g++) {
                __half2 h2 = __floats2half2_rn(f[2 * g], f[2 * g + 1]);
                hv[g] = *(uint32_t*)&h2;
            }
            uint64_t* dst = (uint64_t*)&As[buf][row][(qlb + p) * 12];
            dst[0] = (uint64_t)hv[0] | ((uint64_t)hv[1] << 32);
            dst[1] = (uint64_t)hv[2] | ((uint64_t)hv[3] << 32);
            dst[2] = (uint64_t)hv[4] | ((uint64_t)hv[5] << 32);
        }
    };
    // stage B chunk (64 d x 96 halves = 768 uint4, 6 per thread) from regs
    auto stageB = [&](const uint4* nB, int buf) {
        #pragma unroll
        for (int r = 0; r < 6; r++) {
            int idx = tid + 128 * r;
            int d   = idx / 12;
            int kc  = idx - d * 12;
            *(uint4*)&Bs[buf][d][kc * 8] = nB[r];
        }
    };
    auto loadB = [&](uint4* nB, int c) {
        #pragma unroll
        for (int r = 0; r < 6; r++) {
            int idx = tid + 128 * r;
            int d   = idx / 12;
            int kc  = idx - d * 12;
            nB[r] = *(const uint4*)&g_bh[d * KSL + c * CHUNK_K + kc * 8];
        }
    };

    // ---- prologue: stage chunk 0, prefetch chunk 1 ----
    uint4 nB[6];
    loadB(nB, 0);
    float2 nAng = *(const float2*)&g_angle[(r0 + row) * Q_ + qlb];
    featgen(nAng, 0);
    stageB(nB, 0);
    loadB(nB, 1);
    nAng = *(const float2*)&g_angle[(r0 + row) * Q_ + 8 + qlb];
    __syncthreads();

    for (int c = 0; c < NCHUNK; c++) {
        // ---- stage chunk c+1 into alt buffers (overlaps MMA below) ----
        if (c < NCHUNK - 1) {
            featgen(nAng, (c + 1) & 1);
            stageB(nB, (c + 1) & 1);
            if (c < NCHUNK - 2) {
                loadB(nB, c + 2);
                nAng = *(const float2*)&g_angle[(r0 + row) * Q_ + (c + 2) * 8 + qlb];
            }
        }

        // ---- MMA(c): 6 ktiles x (2m x 2n) ----
        uint32_t asb = smem_u32(&As[c & 1][0][0]);
        const __half (*Bsv)[KPD2] = Bs[c & 1];
        #pragma unroll
        for (int kt = 0; kt < 6; kt++) {
            int k0 = kt * 16 + cc;
            uint32_t A0[4], A1[4];
            ldsm_x4(A0, asb + (uint32_t)((lrow * KPD2 + kt * 16 + lco) * 2));
            ldsm_x4(A1, asb + (uint32_t)(((16 + lrow) * KPD2 + kt * 16 + lco) * 2));
            int d0 = w * 16 + ra;
            uint32_t Bf0[2], Bf1[2];
            Bf0[0] = *(const uint32_t*)&Bsv[d0][k0];
            Bf0[1] = *(const uint32_t*)&Bsv[d0][k0 + 8];
            Bf1[0] = *(const uint32_t*)&Bsv[d0 + 8][k0];
            Bf1[1] = *(const uint32_t*)&Bsv[d0 + 8][k0 + 8];
            mma16816(acc[0][0], A0, Bf0);
            mma16816(acc[0][1], A0, Bf1);
            mma16816(acc[1][0], A1, Bf0);
            mma16816(acc[1][1], A1, Bf1);
        }
        __syncthreads();
    }

    // ---- epilogue ----
    int orow = r0 + ra;
    int ocol = w * 16 + cc;
    #pragma unroll
    for (int m = 0; m < 2; m++) {
        #pragma unroll
        for (int nt = 0; nt < 2; nt++) {
            float* a4 = acc[m][nt];
            int rr  = orow + m * 16;
            int ccg = ocol + nt * 8;
            *(float2*)&out[rr * DOUT + ccg]       = make_float2(a4[0], a4[1]);
            *(float2*)&out[(rr + 8) * DOUT + ccg] = make_float2(a4[2], a4[3]);
        }
    }
}

// ---------------------------------------------------------------------------
extern "C" void kernel_launch(void* const* d_in, const int* in_sizes, int n_in,
                              void* d_out, int out_size) {
    const float* X0   = (const float*)d_in[0];
    const float* tvec = (const float*)d_in[1];
    const float* Wc_w = (const float*)d_in[2];
    const float* Wc_b = (const float*)d_in[3];
    const float* wvec = (const float*)d_in[4];
    const float* A    = (const float*)d_in[5];
    const float* Bp   = (const float*)d_in[6];
    float* out = (float*)d_out;

    angle_kernel<<<ROWS / 32, 128>>>(X0, Wc_w, Wc_b, wvec, tvec, A, Bp);
    fuse_kernel<<<ROWS / 32, 128>>>(out);
}

// round 13
// speedup vs baseline: 1.4674x; 1.0822x over previous
#include <cuda_runtime.h>
#include <cuda_fp16.h>
#include <cstdint>

// Problem shape (fixed per metadata):
//   X0 [4,1024,256] f32, t [4,1] f32, Wc_w [128,256] f32, Wc_b [128] f32,
//   w [128] f32, A [64,128,6] f32, Bp [64,128,6] f32  ->  out [4,1024,64] f32
#define B_   4
#define S_   1024
#define ROWS 4096        // B_*S_
#define DIN  256
#define Q_   128
#define KF   6
#define DOUT 64
#define KSL  1536        // GEMM2: 1 fp16 slot per feature

// Scratch (no device allocs allowed)
__device__ float  g_angle[ROWS * Q_];          // 2 MB
__device__ __half g_bh[DOUT * KSL];            // 192 KB  [d][k] fp16 coeffs

// ---------------------------------------------------------------------------
// m16n8k16 fp16 MMA + ldmatrix helpers
// ---------------------------------------------------------------------------
__device__ __forceinline__ void mma16816(float* c, const uint32_t* a,
                                         const uint32_t* b) {
    asm volatile(
        "mma.sync.aligned.m16n8k16.row.col.f32.f16.f16.f32 "
        "{%0,%1,%2,%3}, {%4,%5,%6,%7}, {%8,%9}, {%0,%1,%2,%3};"
        : "+f"(c[0]), "+f"(c[1]), "+f"(c[2]), "+f"(c[3])
        : "r"(a[0]), "r"(a[1]), "r"(a[2]), "r"(a[3]), "r"(b[0]), "r"(b[1]));
}
__device__ __forceinline__ void ldsm_x4(uint32_t* r, uint32_t addr) {
    asm volatile("ldmatrix.sync.aligned.m8n8.x4.shared.b16 {%0,%1,%2,%3}, [%4];"
                 : "=r"(r[0]), "=r"(r[1]), "=r"(r[2]), "=r"(r[3]) : "r"(addr));
}
__device__ __forceinline__ uint32_t smem_u32(const void* p) {
    uint32_t a;
    asm("{ .reg .u64 t; cvta.to.shared.u64 t, %1; cvt.u32.u64 %0, t; }"
        : "=r"(a) : "l"(p));
    return a;
}

// ---------------------------------------------------------------------------
// Kernel 1: angle GEMM (R12 variant — measured ~8.2us).
// 128 CTAs x 128 threads, 32 rows/CTA, K=256 f32 in 8 chunks of 32.
// INLINE W split. Double-buffered A/B smem, ONE barrier per chunk:
// stage(c+1) + LDG(c+2) overlap MMA(c). A frags via ldmatrix.x4.
// Products: xh*wh + xh*wl + xl*wh (xl*wl dropped, <=2^-22 rel).
// Tail: 384-element slice of the A,Bp fold (g_bh) per CTA.
// ---------------------------------------------------------------------------
#define KP1 72

__global__ __launch_bounds__(128) void angle_kernel(
    const float* __restrict__ X0, const float* __restrict__ W,
    const float* __restrict__ bias, const float* __restrict__ wvec,
    const float* __restrict__ tvec,
    const float* __restrict__ A, const float* __restrict__ Bp)
{
    __shared__ __align__(16) __half Ws1[2][Q_][KP1];   // 36 KB
    __shared__ __align__(16) __half Ax1[2][32][KP1];   //  9.2 KB

    int tid  = threadIdx.x;
    int lane = tid & 31;
    int w    = tid >> 5;              // warp 0..3, q range w*32 .. +31
    int r0   = blockIdx.x * 32;
    int ra   = lane >> 2;
    int cc   = 2 * (lane & 3);
    int lrow = (lane & 7) + ((lane >> 3) & 1) * 8;   // ldmatrix row-in-tile
    int lco  = (lane >> 4) * 8;                      // ldmatrix col offset

    float acc[2][4][4] = {};          // [mtile][ntile][frag]
    int xrow = tid >> 2;              // A staging row 0..31
    int kgrp = (tid & 3) * 8;         // f32 k offset (8 floats/thread)

    // split 8 f32 of X -> xh cols kgrp.., xl cols 32+kgrp..
    auto stageA = [&](const float4& x0, const float4& x1, int buf) {
        float xf[8] = {x0.x, x0.y, x0.z, x0.w, x1.x, x1.y, x1.z, x1.w};
        uint32_t ph[4], pl[4];
        #pragma unroll
        for (int j = 0; j < 4; j++) {
            float a0 = xf[2 * j], a1 = xf[2 * j + 1];
            __half h0 = __float2half_rn(a0);
            __half l0 = __float2half_rn(a0 - __half2float(h0));
            __half h1 = __float2half_rn(a1);
            __half l1 = __float2half_rn(a1 - __half2float(h1));
            __half2 hh = __halves2half2(h0, h1);
            __half2 ll = __halves2half2(l0, l1);
            ph[j] = *(uint32_t*)&hh;
            pl[j] = *(uint32_t*)&ll;
        }
        *(uint4*)&Ax1[buf][xrow][kgrp]      = make_uint4(ph[0], ph[1], ph[2], ph[3]);
        *(uint4*)&Ax1[buf][xrow][32 + kgrp] = make_uint4(pl[0], pl[1], pl[2], pl[3]);
    };
    // split 32 f32 of W (q = tid) -> wh cols 0-31, wl cols 32-63
    auto stageW = [&](const float4* nwf, int buf) {
        const float* wf = (const float*)nwf;
        uint32_t whp[16], wlp[16];
        #pragma unroll
        for (int j = 0; j < 16; j++) {
            float a0 = wf[2 * j], a1 = wf[2 * j + 1];
            __half h0 = __float2half_rn(a0);
            __half l0 = __float2half_rn(a0 - __half2float(h0));
            __half h1 = __float2half_rn(a1);
            __half l1 = __float2half_rn(a1 - __half2float(h1));
            __half2 hh = __halves2half2(h0, h1);
            __half2 ll = __halves2half2(l0, l1);
            whp[j] = *(uint32_t*)&hh;
            wlp[j] = *(uint32_t*)&ll;
        }
        #pragma unroll
        for (int g = 0; g < 4; g++) {
            *(uint4*)&Ws1[buf][tid][g * 8] =
                make_uint4(whp[4*g], whp[4*g+1], whp[4*g+2], whp[4*g+3]);
            *(uint4*)&Ws1[buf][tid][32 + g * 8] =
                make_uint4(wlp[4*g], wlp[4*g+1], wlp[4*g+2], wlp[4*g+3]);
        }
    };

    // ---- prologue: stage chunk 0, prefetch chunk 1 ----
    float4 nx0 = *(const float4*)&X0[(r0 + xrow) * DIN + kgrp];
    float4 nx1 = *(const float4*)&X0[(r0 + xrow) * DIN + kgrp + 4];
    float4 nwf[8];
    #pragma unroll
    for (int j = 0; j < 8; j++)
        nwf[j] = *(const float4*)&W[tid * DIN + j * 4];
    stageA(nx0, nx1, 0);
    stageW(nwf, 0);
    nx0 = *(const float4*)&X0[(r0 + xrow) * DIN + 32 + kgrp];
    nx1 = *(const float4*)&X0[(r0 + xrow) * DIN + 32 + kgrp + 4];
    #pragma unroll
    for (int j = 0; j < 8; j++)
        nwf[j] = *(const float4*)&W[tid * DIN + 32 + j * 4];
    __syncthreads();

    for (int c = 0; c < 8; c++) {
        // ---- stage chunk c+1 into alt buffers (overlaps MMA below) ----
        if (c < 7) {
            stageA(nx0, nx1, (c + 1) & 1);
            stageW(nwf, (c + 1) & 1);
            if (c < 6) {
                nx0 = *(const float4*)&X0[(r0 + xrow) * DIN + (c + 2) * 32 + kgrp];
                nx1 = *(const float4*)&X0[(r0 + xrow) * DIN + (c + 2) * 32 + kgrp + 4];
                #pragma unroll
                for (int j = 0; j < 8; j++)
                    nwf[j] = *(const float4*)&W[tid * DIN + (c + 2) * 32 + j * 4];
            }
        }

        // ---- MMA(c): 2 ktiles x {xh*wh, xh*wl, xl*wh} x 2m x 4n ----
        uint32_t axb = smem_u32(&Ax1[c & 1][0][0]);
        const __half (*Ws)[KP1] = Ws1[c & 1];
        #pragma unroll
        for (int kt = 0; kt < 2; kt++) {
            int khb = kt * 16;            // xh col base
            int klb = 32 + kt * 16;       // xl col base
            uint32_t A0h[4], A1h[4], A0l[4], A1l[4];
            ldsm_x4(A0h, axb + (uint32_t)((lrow * KP1 + khb + lco) * 2));
            ldsm_x4(A1h, axb + (uint32_t)(((16 + lrow) * KP1 + khb + lco) * 2));
            ldsm_x4(A0l, axb + (uint32_t)((lrow * KP1 + klb + lco) * 2));
            ldsm_x4(A1l, axb + (uint32_t)(((16 + lrow) * KP1 + klb + lco) * 2));
            int kh = khb + cc, kl = klb + cc;
            #pragma unroll
            for (int n = 0; n < 4; n++) {
                int q0 = w * 32 + n * 8 + ra;
                uint32_t Bh[2], Bl[2];
                Bh[0] = *(const uint32_t*)&Ws[q0][kh];
                Bh[1] = *(const uint32_t*)&Ws[q0][kh + 8];
                Bl[0] = *(const uint32_t*)&Ws[q0][kl];
                Bl[1] = *(const uint32_t*)&Ws[q0][kl + 8];
                mma16816(acc[0][n], A0h, Bh);   // xh*wh
                mma16816(acc[1][n], A1h, Bh);
                mma16816(acc[0][n], A0h, Bl);   // xh*wl
                mma16816(acc[1][n], A1h, Bl);
                mma16816(acc[0][n], A0l, Bh);   // xl*wh
                mma16816(acc[1][n], A1l, Bh);
            }
        }
        __syncthreads();
    }

    // ---- epilogue: + bias + w*t -> g_angle ----
    float tb = tvec[r0 >> 10];
    #pragma unroll
    for (int n = 0; n < 4; n++) {
        int q = w * 32 + n * 8 + cc;
        float b0 = __ldg(&bias[q])     + __ldg(&wvec[q]) * tb;
        float b1 = __ldg(&bias[q + 1]) + __ldg(&wvec[q + 1]) * tb;
        #pragma unroll
        for (int m = 0; m < 2; m++) {
            int rr = r0 + m * 16 + ra;
            float* a4 = acc[m][n];
            *(float2*)&g_angle[rr * Q_ + q]       = make_float2(a4[0] + b0, a4[1] + b1);
            *(float2*)&g_angle[(rr + 8) * Q_ + q] = make_float2(a4[2] + b0, a4[3] + b1);
        }
    }

    // ---- tail: this CTA's 384-element slice of the A,Bp fold (g_bh) ----
    #pragma unroll
    for (int j = 0; j < 3; j++) {
        int i = blockIdx.x * 384 + j * 128 + tid;     // 0 .. 49151
        int d   = i / (Q_ * KF);
        int rem = i - d * (Q_ * KF);                  // q*6 + h
        float a = A[i], b = Bp[i];
        float sb, cb;
        __sincosf(b, &sb, &cb);
        __half2 hv = __floats2half2_rn(a * cb, a * sb);
        *(uint32_t*)&g_bh[d * KSL + rem * 2] = *(uint32_t*)&hv;
    }
}

// ---------------------------------------------------------------------------
// Kernel 2: fused feature-gen + HMMA GEMM2 (R10 variant — measured 13.5us).
// 128 CTAs x 128 threads, 32 rows/CTA. 8 chunks of 16 q (192 k-slots).
// smem stride 400B -> conflict-free fragment LDS/STS.
// ---------------------------------------------------------------------------
#define KPAD   200
#define CHUNK_K 192
#define NCHUNK  8

__global__ __launch_bounds__(128) void fuse_kernel(float* __restrict__ out)
{
    __shared__ __half As[32][KPAD];   // 12.8 KB
    __shared__ __half Bs[64][KPAD];   // 25.6 KB

    int tid  = threadIdx.x;
    int lane = tid & 31;
    int w    = tid >> 5;
    int r0   = blockIdx.x * 32;
    int row  = lane;                  // featgen row
    int qlb  = w * 4;                 // featgen local-q base (4 q per thread)

    float acc[2][2][4] = {};

    // prologue prefetch: chunk 0
    uint4 nB[12];
    #pragma unroll
    for (int r = 0; r < 12; r++) {
        int idx = tid + 128 * r;
        int d   = idx / 24;
        int kc  = idx - d * 24;
        nB[r] = *(const uint4*)&g_bh[d * KSL + kc * 8];
    }
    float4 nAng = *(const float4*)&g_angle[(r0 + row) * Q_ + qlb];

    for (int c = 0; c < NCHUNK; c++) {
        // ---- features for 4 q's -> fp16, STS ----
        {
            float af[4] = {nAng.x, nAng.y, nAng.z, nAng.w};
            #pragma unroll
            for (int p = 0; p < 4; p++) {
                float a = af[p];
                // Cody-Waite reduction mod 2*pi (C1=6.28125: 9 mantissa bits)
                float n = rintf(a * 0.15915494309189535f);
                float rr = fmaf(n, -6.28125f, a);
                rr = fmaf(n, -1.9353071795864769e-3f, rr);
                float s1, c1;
                __sincosf(rr, &s1, &c1);
                float f[12];
                f[0] = s1; f[1] = c1;
                float sk = s1, ck = c1;
                #pragma unroll
                for (int h = 1; h < KF; h++) {
                    float sn = fmaf(sk, c1, ck * s1);
                    float cn = fmaf(ck, c1, -sk * s1);
                    f[2 * h] = sn; f[2 * h + 1] = cn;
                    sk = sn; ck = cn;
                }
                uint32_t hv[6];
                #pragma unroll
                for (int g = 0; g < 6; g++) {
                    __half2 h2 = __floats2half2_rn(f[2 * g], f[2 * g + 1]);
                    hv[g] = *(uint32_t*)&h2;
                }
                int kl = (qlb + p) * 12;
                uint64_t* dst = (uint64_t*)&As[row][kl];
                dst[0] = (uint64_t)hv[0] | ((uint64_t)hv[1] << 32);
                dst[1] = (uint64_t)hv[2] | ((uint64_t)hv[3] << 32);
                dst[2] = (uint64_t)hv[4] | ((uint64_t)hv[5] << 32);
            }
        }
        // ---- stage B chunk ----
        #pragma unroll
        for (int r = 0; r < 12; r++) {
            int idx = tid + 128 * r;
            int d   = idx / 24;
            int kc  = idx - d * 24;
            *(uint4*)&Bs[d][kc * 8] = nB[r];
        }
        __syncthreads();

        // ---- prefetch next chunk ----
        if (c < NCHUNK - 1) {
            #pragma unroll
            for (int r = 0; r < 12; r++) {
                int idx = tid + 128 * r;
                int d   = idx / 24;
                int kc  = idx - d * 24;
                nB[r] = *(const uint4*)&g_bh[d * KSL + (c + 1) * CHUNK_K + kc * 8];
            }
            nAng = *(const float4*)&g_angle[(r0 + row) * Q_ + (c + 1) * 16 + qlb];
        }

        // ---- MMA: 12 ktiles x (2m x 2n) ----
        int ra = lane >> 2;
        int cc = 2 * (lane & 3);
        #pragma unroll
        for (int kt = 0; kt < 12; kt++) {
            int k0 = kt * 16 + cc;
            uint32_t A0[4], A1[4], Bf0[2], Bf1[2];
            A0[0] = *(const uint32_t*)&As[ra][k0];
            A0[1] = *(const uint32_t*)&As[ra + 8][k0];
            A0[2] = *(const uint32_t*)&As[ra][k0 + 8];
            A0[3] = *(const uint32_t*)&As[ra + 8][k0 + 8];
            A1[0] = *(const uint32_t*)&As[ra + 16][k0];
            A1[1] = *(const uint32_t*)&As[ra + 24][k0];
            A1[2] = *(const uint32_t*)&As[ra + 16][k0 + 8];
            A1[3] = *(const uint32_t*)&As[ra + 24][k0 + 8];
            int d0 = w * 16 + ra;
            Bf0[0] = *(const uint32_t*)&Bs[d0][k0];
            Bf0[1] = *(const uint32_t*)&Bs[d0][k0 + 8];
            Bf1[0] = *(const uint32_t*)&Bs[d0 + 8][k0];
            Bf1[1] = *(const uint32_t*)&Bs[d0 + 8][k0 + 8];
            mma16816(acc[0][0], A0, Bf0);
            mma16816(acc[0][1], A0, Bf1);
            mma16816(acc[1][0], A1, Bf0);
            mma16816(acc[1][1], A1, Bf1);
        }
        __syncthreads();
    }

    // ---- epilogue ----
    int orow = r0 + (lane >> 2);
    int ocol = w * 16 + 2 * (lane & 3);
    #pragma unroll
    for (int m = 0; m < 2; m++) {
        #pragma unroll
        for (int nt = 0; nt < 2; nt++) {
            float* a4 = acc[m][nt];
            int rr  = orow + m * 16;
            int ccg = ocol + nt * 8;
            *(float2*)&out[rr * DOUT + ccg]       = make_float2(a4[0], a4[1]);
            *(float2*)&out[(rr + 8) * DOUT + ccg] = make_float2(a4[2], a4[3]);
        }
    }
}

// ---------------------------------------------------------------------------
extern "C" void kernel_launch(void* const* d_in, const int* in_sizes, int n_in,
                              void* d_out, int out_size) {
    const float* X0   = (const float*)d_in[0];
    const float* tvec = (const float*)d_in[1];
    const float* Wc_w = (const float*)d_in[2];
    const float* Wc_b = (const float*)d_in[3];
    const float* wvec = (const float*)d_in[4];
    const float* A    = (const float*)d_in[5];
    const float* Bp   = (const float*)d_in[6];
    float* out = (float*)d_out;

    angle_kernel<<<ROWS / 32, 128>>>(X0, Wc_w, Wc_b, wvec, tvec, A, Bp);
    fuse_kernel<<<ROWS / 32, 128>>>(out);
}